// round 3
// baseline (speedup 1.0000x reference)
#include <cuda_runtime.h>

// Problem constants
#define BB    256
#define HH    512
#define G4    2048
#define SRCT  512
#define INP   64
#define TGTT  96

// Kernel config
#define NBLK  128
#define NTHR  512
#define KC    32

// ---------------- device globals (scratch; no allocations allowed) ----------
static __device__ __align__(16) float g_h[2][2][BB * HH];   // [layer][parity][b*H+u]
static __device__ __align__(16) float g_c[2][BB * HH];      // [layer][b*H+u]
static __device__ __align__(16) float g_x[BB];              // decoder scalar input
static __device__ __align__(16) float g_fc[BB * HH];        // fc hidden
static __device__ __align__(16) float g_part[3 * BB * G4];  // split-K partials
static __device__ int g_flag[NBLK];
static __device__ unsigned g_count;
static __device__ volatile unsigned g_sense;

struct SM {
    float hs[KC][128];
    float ws[KC][128];
};

// ---------------- helpers ---------------------------------------------------
__device__ __forceinline__ float sigm(float x) {
    return 1.0f / (1.0f + __expf(-x));
}
__device__ __forceinline__ float tanh_f(float x) {
    return 2.0f / (1.0f + __expf(-2.0f * x)) - 1.0f;
}

// grid-wide barrier: monotonic generation counter (reset by prologue kernel)
__device__ __forceinline__ void gsync() {
    __threadfence();
    __syncthreads();
    if (threadIdx.x == 0) {
        unsigned a = atomicAdd(&g_count, 1u);
        unsigned target = a / NBLK + 1u;
        if ((a % NBLK) == (NBLK - 1)) {
            __threadfence();
            g_sense = target;
        } else {
            while (g_sense < target) { __nanosleep(64); }
        }
        __threadfence();
    }
    __syncthreads();
}

template <bool CG, bool RELU>
__device__ __forceinline__ void ldx8(float* r, const float* p) {
    float4 a, b;
    if (CG) {
        a = __ldcg((const float4*)p);
        b = __ldcg(((const float4*)p) + 1);
    } else {
        a = __ldg((const float4*)p);
        b = __ldg(((const float4*)p) + 1);
    }
    if (RELU) {
        a.x = fmaxf(a.x, 0.f); a.y = fmaxf(a.y, 0.f);
        a.z = fmaxf(a.z, 0.f); a.w = fmaxf(a.w, 0.f);
        b.x = fmaxf(b.x, 0.f); b.y = fmaxf(b.y, 0.f);
        b.z = fmaxf(b.z, 0.f); b.w = fmaxf(b.w, 0.f);
    }
    r[0] = a.x; r[1] = a.y; r[2] = a.z; r[3] = a.w;
    r[4] = b.x; r[5] = b.y; r[6] = b.z; r[7] = b.w;
}

__device__ __forceinline__ void ldw8(float* r, const float* p) {
    float4 a = __ldg((const float4*)p);
    float4 b = __ldg(((const float4*)p) + 1);
    r[0] = a.x; r[1] = a.y; r[2] = a.z; r[3] = a.w;
    r[4] = b.x; r[5] = b.y; r[6] = b.z; r[7] = b.w;
}

__device__ __forceinline__ void fma8(float* a8, float av,
                                     const float4& w0, const float4& w1) {
    a8[0] += av * w0.x; a8[1] += av * w0.y; a8[2] += av * w0.z; a8[3] += av * w0.w;
    a8[4] += av * w1.x; a8[5] += av * w1.y; a8[6] += av * w1.z; a8[7] += av * w1.w;
}

// Accumulate acc[4 b-rows][8 cols] += X_tile * W_tile^T over nt k-tiles.
// Block tile 128 rows x 128 cols; 512 threads; thread tile 4x8.
// px: this thread's loader pointer into X (row b_base+lrow, col k0+kofs).
// pw: this thread's loader pointer into W (row for panel col lrow, col k0+kofs).
template <bool CG, bool RELU>
__device__ __forceinline__ void mm_accum(float (&acc)[4][8], SM& sm,
                                         const float* px, const float* pw,
                                         int nt, int tx, int ty,
                                         int lrow, int kofs) {
    float rx[8], rw[8];
    ldx8<CG, RELU>(rx, px);
    ldw8(rw, pw);
    for (int kt = 0; kt < nt; kt++) {
        __syncthreads();
#pragma unroll
        for (int i = 0; i < 8; i++) {
            sm.hs[kofs + i][lrow] = rx[i];
            sm.ws[kofs + i][lrow] = rw[i];
        }
        __syncthreads();
        if (kt + 1 < nt) {
            ldx8<CG, RELU>(rx, px + (kt + 1) * KC);
            ldw8(rw, pw + (kt + 1) * KC);
        }
        const float4* h4 = reinterpret_cast<const float4*>(&sm.hs[0][0]);
        const float4* w4 = reinterpret_cast<const float4*>(&sm.ws[0][0]);
#pragma unroll
        for (int kk = 0; kk < KC; kk++) {
            float4 a  = h4[kk * 32 + ty];
            float4 w0 = w4[kk * 32 + tx * 2];
            float4 w1 = w4[kk * 32 + tx * 2 + 1];
            fma8(acc[0], a.x, w0, w1);
            fma8(acc[1], a.y, w0, w1);
            fma8(acc[2], a.z, w0, w1);
            fma8(acc[3], a.w, w0, w1);
        }
    }
}

// writer side of split-K: store partial + raise flag
__device__ __forceinline__ void store_partial(const float (&acc)[4][8],
                                              long rowstride, int b_base, int jb,
                                              int ks, int ty, int tx,
                                              int tid, int seq) {
    float* pp = g_part + (long)(ks - 1) * (BB * G4);
#pragma unroll
    for (int i = 0; i < 4; i++) {
        long o = (long)(b_base + ty * 4 + i) * rowstride + jb + tx * 8;
        __stcg((float4*)(pp + o), make_float4(acc[i][0], acc[i][1], acc[i][2], acc[i][3]));
        __stcg((float4*)(pp + o + 4), make_float4(acc[i][4], acc[i][5], acc[i][6], acc[i][7]));
    }
    __syncthreads();
    if (tid == 0) {
        __threadfence();
        ((volatile int*)g_flag)[blockIdx.x] = seq;
    }
}

// reader side: wait for nw partner flags, then add their partials into acc
__device__ __forceinline__ void combine_partials(float (&acc)[4][8],
                                                 long rowstride, int b_base, int jb,
                                                 int nw, int ty, int tx,
                                                 int tid, int seq) {
    if (tid == 0) {
        int base = blockIdx.x;
        for (int s = 1; s <= nw; s++) {
            while (((volatile int*)g_flag)[base + s] < seq) { __nanosleep(32); }
        }
    }
    __syncthreads();
    __threadfence();
#pragma unroll
    for (int i = 0; i < 4; i++) {
        long o = (long)(b_base + ty * 4 + i) * rowstride + jb + tx * 8;
#pragma unroll
        for (int s = 0; s < 3; s++) {
            if (s < nw) {
                const float* pp = g_part + (long)s * (BB * G4);
                float4 q0 = __ldcg((const float4*)(pp + o));
                float4 q1 = __ldcg((const float4*)(pp + o + 4));
                acc[i][0] += q0.x; acc[i][1] += q0.y; acc[i][2] += q0.z; acc[i][3] += q0.w;
                acc[i][4] += q1.x; acc[i][5] += q1.y; acc[i][6] += q1.z; acc[i][7] += q1.w;
            }
        }
    }
}

// One LSTM layer step. Block tile: 128 b-rows x 32 cells x 4 gates, split-K-4.
// Kx: 64 (encoder L0 input), 512 (h input), 1 (decoder scalar), 0 (none).
__device__ __forceinline__ void lstm_layer(SM& sm,
                                           const float* xbase, long xld,
                                           int Kx, bool xcg,
                                           const float* Wih, const float* Whh,
                                           const float* bih, const float* bhh,
                                           const float* hprev, float* cbuf,
                                           float* hnext,
                                           int b_base, int jb, int u_base, int ks,
                                           int seq, int tx, int ty,
                                           int lrow, int kofs, int tid) {
    float acc[4][8];
    const int u0 = u_base + tx * 2;

    if (ks == 0) {
#pragma unroll
        for (int q = 0; q < 8; q++) {
            int g = q & 3, uo = q >> 2;
            float bb = __ldg(bih + g * HH + u0 + uo) + __ldg(bhh + g * HH + u0 + uo);
            acc[0][q] = bb; acc[1][q] = bb; acc[2][q] = bb; acc[3][q] = bb;
        }
    } else {
#pragma unroll
        for (int q = 0; q < 8; q++) {
            acc[0][q] = 0.f; acc[1][q] = 0.f; acc[2][q] = 0.f; acc[3][q] = 0.f;
        }
    }

    const int wg = lrow & 3;                 // gate of this panel column
    const int wu = u_base + (lrow >> 2);     // cell of this panel column

    // ---- input GEMM ----
    if (Kx >= 64) {
        const int nsplit = (Kx == 64) ? 2 : 4;
        const int xper = Kx / nsplit;        // 32 or 128
        if (ks < nsplit) {
            const int k0 = ks * xper;
            const float* px = xbase + (long)(b_base + lrow) * xld + k0 + kofs;
            const float* pw = Wih + (long)(wg * HH + wu) * Kx + k0 + kofs;
            if (xcg) mm_accum<true, false>(acc, sm, px, pw, xper / KC, tx, ty, lrow, kofs);
            else     mm_accum<false, false>(acc, sm, px, pw, xper / KC, tx, ty, lrow, kofs);
        }
    } else if (Kx == 1 && ks == 0) {
        float wv[8];
#pragma unroll
        for (int q = 0; q < 8; q++) {
            int g = q & 3, uo = q >> 2;
            wv[q] = __ldg(Wih + g * HH + u0 + uo);
        }
#pragma unroll
        for (int i = 0; i < 4; i++) {
            float xv = __ldcg(&g_x[b_base + ty * 4 + i]);
#pragma unroll
            for (int q = 0; q < 8; q++) acc[i][q] += xv * wv[q];
        }
    }

    // ---- recurrent GEMM (K = 512, split 4 ways) ----
    {
        const int k0 = ks * (HH / 4);
        const float* px = hprev + (long)(b_base + lrow) * HH + k0 + kofs;
        const float* pw = Whh + (long)(wg * HH + wu) * HH + k0 + kofs;
        mm_accum<true, false>(acc, sm, px, pw, (HH / 4) / KC, tx, ty, lrow, kofs);
    }

    if (ks != 0) {
        store_partial(acc, G4, b_base, jb, ks, ty, tx, tid, seq);
        return;
    }

    combine_partials(acc, G4, b_base, jb, 3, ty, tx, tid, seq);

    // ---- activation + state update (2 cells per thread) ----
#pragma unroll
    for (int i = 0; i < 4; i++) {
        const int b = b_base + ty * 4 + i;
        const long co = (long)b * HH + u0;
        float i0 = sigm(acc[i][0]), f0 = sigm(acc[i][1]);
        float g0 = tanh_f(acc[i][2]), o0 = sigm(acc[i][3]);
        float i1 = sigm(acc[i][4]), f1 = sigm(acc[i][5]);
        float g1 = tanh_f(acc[i][6]), o1 = sigm(acc[i][7]);
        float2 cc = __ldcg((const float2*)(cbuf + co));
        float c0 = f0 * cc.x + i0 * g0;
        float c1 = f1 * cc.y + i1 * g1;
        __stcg((float2*)(cbuf + co), make_float2(c0, c1));
        __stcg((float2*)(hnext + co), make_float2(o0 * tanh_f(c0), o1 * tanh_f(c1)));
    }
}

// ---------------- prologue: reset barrier + states --------------------------
__global__ void reset_kernel(const float* __restrict__ tgt) {
    long idx = (long)blockIdx.x * blockDim.x + threadIdx.x;
    long stride = (long)gridDim.x * blockDim.x;
    float* hp = &g_h[0][0][0];
    for (long i = idx; i < 2L * 2 * BB * HH; i += stride) hp[i] = 0.f;
    float* cp = &g_c[0][0];
    for (long i = idx; i < 2L * BB * HH; i += stride) cp[i] = 0.f;
    if (idx < BB) g_x[idx] = tgt[idx * TGTT];  // tgt[:,0]
    if (idx < NBLK) g_flag[idx] = 0;
    if (idx == 0) { g_count = 0u; g_sense = 0u; }
}

// ---------------- main persistent kernel ------------------------------------
__global__ __launch_bounds__(NTHR, 1) void seq2seq_kernel(
    const float* __restrict__ src, const float* __restrict__ tgt,
    const float* __restrict__ eWih0, const float* __restrict__ eWhh0,
    const float* __restrict__ ebih0, const float* __restrict__ ebhh0,
    const float* __restrict__ dWih0, const float* __restrict__ dWhh0,
    const float* __restrict__ dbih0, const float* __restrict__ dbhh0,
    const float* __restrict__ eWih1, const float* __restrict__ eWhh1,
    const float* __restrict__ ebih1, const float* __restrict__ ebhh1,
    const float* __restrict__ dWih1, const float* __restrict__ dWhh1,
    const float* __restrict__ dbih1, const float* __restrict__ dbhh1,
    const float* __restrict__ fW0, const float* __restrict__ fb0,
    const float* __restrict__ fW1, const float* __restrict__ fb1,
    float* __restrict__ out) {
    __shared__ SM sm;

    const int tid = threadIdx.x;
    const int tx = tid & 15;          // 8 output cols (2 cells x 4 gates)
    const int ty = tid >> 4;          // 4 output rows
    const int lrow = tid & 127;       // loader: panel column / x row
    const int kofs = (tid >> 7) * 8;  // loader: k offset within KC

    const int tile = blockIdx.x >> 2;     // 0..31
    const int ks = blockIdx.x & 3;        // split-K id
    const int b_base = (tile >> 4) * 128; // 0 or 128
    const int jb = (tile & 15) * 128;     // gate-col base
    const int u_base = jb >> 2;           // cell base (32 cells per tile)

    int par = 0;
    int seq = 0;

    // ---------------- encoder ----------------
    for (int t = 0; t < SRCT; t++) {
        seq++;
        lstm_layer(sm, src + (long)t * INP, (long)SRCT * INP, INP, false,
                   eWih0, eWhh0, ebih0, ebhh0,
                   g_h[0][par], g_c[0], g_h[0][par ^ 1],
                   b_base, jb, u_base, ks, seq, tx, ty, lrow, kofs, tid);
        gsync();
        seq++;
        lstm_layer(sm, g_h[0][par ^ 1], HH, HH, true,
                   eWih1, eWhh1, ebih1, ebhh1,
                   g_h[1][par], g_c[1], g_h[1][par ^ 1],
                   b_base, jb, u_base, ks, seq, tx, ty, lrow, kofs, tid);
        gsync();
        par ^= 1;
    }

    // ---------------- decoder ----------------
    for (int t = 0; t < TGTT; t++) {
        seq++;
        lstm_layer(sm, nullptr, 0, 1, true,
                   dWih0, dWhh0, dbih0, dbhh0,
                   g_h[0][par], g_c[0], g_h[0][par ^ 1],
                   b_base, jb, u_base, ks, seq, tx, ty, lrow, kofs, tid);
        gsync();
        seq++;
        lstm_layer(sm, g_h[0][par ^ 1], HH, HH, true,
                   dWih1, dWhh1, dbih1, dbhh1,
                   g_h[1][par], g_c[1], g_h[1][par ^ 1],
                   b_base, jb, u_base, ks, seq, tx, ty, lrow, kofs, tid);
        gsync();

        // fc0: g_fc = relu( relu(h1) @ W0^T + b0 ). 8 tiles x split-K-4 = 32 blocks.
        seq++;
        if (blockIdx.x < 32) {
            const int ftile = blockIdx.x >> 2;      // 0..7
            const int fks = blockIdx.x & 3;
            const int fb_base = (ftile >> 2) * 128; // 0 or 128
            const int fjb = (ftile & 3) * 128;      // col base within 512
            float acc[4][8];
            if (fks == 0) {
#pragma unroll
                for (int q = 0; q < 8; q++) {
                    float bb = __ldg(fb0 + fjb + tx * 8 + q);
                    acc[0][q] = bb; acc[1][q] = bb; acc[2][q] = bb; acc[3][q] = bb;
                }
            } else {
#pragma unroll
                for (int q = 0; q < 8; q++) {
                    acc[0][q] = 0.f; acc[1][q] = 0.f; acc[2][q] = 0.f; acc[3][q] = 0.f;
                }
            }
            const int k0 = fks * (HH / 4);
            const float* px = g_h[1][par ^ 1] + (long)(fb_base + lrow) * HH + k0 + kofs;
            const float* pw = fW0 + (long)(fjb + lrow) * HH + k0 + kofs;
            mm_accum<true, true>(acc, sm, px, pw, (HH / 4) / KC, tx, ty, lrow, kofs);

            if (fks != 0) {
                store_partial(acc, HH, fb_base, fjb, fks, ty, tx, tid, seq);
            } else {
                combine_partials(acc, HH, fb_base, fjb, 3, ty, tx, tid, seq);
#pragma unroll
                for (int i = 0; i < 4; i++) {
                    const int b = fb_base + ty * 4 + i;
                    const long o = (long)b * HH + fjb + tx * 8;
                    __stcg((float4*)(g_fc + o),
                           make_float4(fmaxf(acc[i][0], 0.f), fmaxf(acc[i][1], 0.f),
                                       fmaxf(acc[i][2], 0.f), fmaxf(acc[i][3], 0.f)));
                    __stcg((float4*)(g_fc + o + 4),
                           make_float4(fmaxf(acc[i][4], 0.f), fmaxf(acc[i][5], 0.f),
                                       fmaxf(acc[i][6], 0.f), fmaxf(acc[i][7], 0.f)));
                }
            }
        }
        gsync();

        // fc1: out[b] = g_fc[b] . W1 + b1 ; becomes next decoder input
        if (blockIdx.x == 0 && tid < BB) {
            const int b = tid;
            const float4* tp = (const float4*)(g_fc + (long)b * HH);
            const float4* wp = (const float4*)fW1;
            float s0 = 0.f, s1 = 0.f, s2 = 0.f, s3 = 0.f;
#pragma unroll 8
            for (int k = 0; k < HH / 4; k++) {
                float4 v = __ldcg(tp + k);
                float4 w = __ldg(wp + k);
                s0 += v.x * w.x; s1 += v.y * w.y;
                s2 += v.z * w.z; s3 += v.w * w.w;
            }
            float o = (s0 + s1) + (s2 + s3) + __ldg(fb1);
            out[(long)b * TGTT + t] = o;
            __stcg(&g_x[b], o);
        }
        gsync();
        par ^= 1;
    }
}

// ---------------- launch ----------------------------------------------------
extern "C" void kernel_launch(void* const* d_in, const int* in_sizes, int n_in,
                              void* d_out, int out_size) {
    const float* src   = (const float*)d_in[0];
    const float* tgt   = (const float*)d_in[1];
    const float* eWih0 = (const float*)d_in[2];
    const float* eWhh0 = (const float*)d_in[3];
    const float* ebih0 = (const float*)d_in[4];
    const float* ebhh0 = (const float*)d_in[5];
    const float* dWih0 = (const float*)d_in[6];
    const float* dWhh0 = (const float*)d_in[7];
    const float* dbih0 = (const float*)d_in[8];
    const float* dbhh0 = (const float*)d_in[9];
    const float* eWih1 = (const float*)d_in[10];
    const float* eWhh1 = (const float*)d_in[11];
    const float* ebih1 = (const float*)d_in[12];
    const float* ebhh1 = (const float*)d_in[13];
    const float* dWih1 = (const float*)d_in[14];
    const float* dWhh1 = (const float*)d_in[15];
    const float* dbih1 = (const float*)d_in[16];
    const float* dbhh1 = (const float*)d_in[17];
    const float* fW0   = (const float*)d_in[18];
    const float* fb0   = (const float*)d_in[19];
    const float* fW1   = (const float*)d_in[20];
    const float* fb1   = (const float*)d_in[21];
    float* out = (float*)d_out;

    reset_kernel<<<512, 256>>>(tgt);
    seq2seq_kernel<<<NBLK, NTHR>>>(src, tgt,
                                   eWih0, eWhh0, ebih0, ebhh0,
                                   dWih0, dWhh0, dbih0, dbhh0,
                                   eWih1, eWhh1, ebih1, ebhh1,
                                   dWih1, dWhh1, dbih1, dbhh1,
                                   fW0, fb0, fW1, fb1, out);
}

// round 5
// speedup vs baseline: 2.4430x; 2.4430x over previous
#include <cuda_runtime.h>
#include <cuda_bf16.h>

#define BB    256
#define HH    512
#define G4    2048
#define SRCT  512
#define INP   64
#define TGTT  96
#define NBLK  128
#define NTHR  256

typedef __nv_bfloat16 bf16;

// smem chunk: A_hi[64][40] | A_lo | B_hi[64][40] | B_lo   (bf16, row stride 40)
#define A_PLANE   5120u
#define B_BASE    10240u
#define B_PLANE   5120u
#define CH_BYTES  20480u
#define SMEM_BYTES (4 * 20480)

// ---------------- device globals ----------------
static __device__ __align__(16) bf16 s_hi[(long)BB*SRCT*INP], s_lo[(long)BB*SRCT*INP];
static __device__ __align__(16) bf16 w_e0i_h[G4*INP], w_e0i_l[G4*INP];
static __device__ __align__(16) bf16 w_e0h_h[G4*HH],  w_e0h_l[G4*HH];
static __device__ __align__(16) bf16 w_e1i_h[G4*HH],  w_e1i_l[G4*HH];
static __device__ __align__(16) bf16 w_e1h_h[G4*HH],  w_e1h_l[G4*HH];
static __device__ __align__(16) bf16 w_d0h_h[G4*HH],  w_d0h_l[G4*HH];
static __device__ __align__(16) bf16 w_d1i_h[G4*HH],  w_d1i_l[G4*HH];
static __device__ __align__(16) bf16 w_d1h_h[G4*HH],  w_d1h_l[G4*HH];
static __device__ __align__(16) bf16 w_f0_h[HH*HH],   w_f0_l[HH*HH];
static __device__ __align__(16) bf16 g_hhi[2][2][BB*HH], g_hlo[2][2][BB*HH];
static __device__ __align__(16) bf16 g_rhhi[BB*HH], g_rhlo[BB*HH];
static __device__ __align__(16) float g_c2[2][BB*HH];
static __device__ __align__(16) float g_x[BB];
static __device__ __align__(16) float g_fc[BB*HH];
static __device__ unsigned g_count;
static __device__ volatile unsigned g_sense;

// ---------------- helpers ----------------
__device__ __forceinline__ float sigm(float x) { return 1.0f / (1.0f + __expf(-x)); }
__device__ __forceinline__ float tanh_f(float x) { return 2.0f / (1.0f + __expf(-2.0f * x)) - 1.0f; }

__device__ __forceinline__ void gsync() {
    __threadfence();
    __syncthreads();
    if (threadIdx.x == 0) {
        unsigned a = atomicAdd(&g_count, 1u);
        unsigned target = a / NBLK + 1u;
        if ((a % NBLK) == (NBLK - 1)) {
            __threadfence();
            g_sense = target;
        } else {
            while (g_sense < target) { __nanosleep(32); }
        }
        __threadfence();
    }
    __syncthreads();
}

__device__ __forceinline__ void st16cg(bf16* p, bf16 v) {
    unsigned short u = __bfloat16_as_ushort(v);
    asm volatile("st.global.cg.u16 [%0], %1;" :: "l"(p), "h"(u) : "memory");
}

// 1024 cp.async tasks: A 64 rows x 4 segs x {hi,lo}; B 64 x 4 x {hi,lo}
__device__ __forceinline__ void load_chunk(unsigned dstbase,
        const bf16* ah, const bf16* al, int lda,
        const bf16* wh, const bf16* wl, int ldw,
        int arow0, int k0, int ubj, bool lstm, int tid) {
#pragma unroll
    for (int it = 0; it < 4; it++) {
        int task = tid + it * NTHR;
        const bf16* src;
        unsigned dst;
        if (task < 512) {
            int plane = task >> 8, idx = task & 255;
            int row = idx >> 2, seg = (idx & 3) << 3;
            src = (plane ? al : ah) + (long)(arow0 + row) * lda + k0 + seg;
            dst = dstbase + plane * A_PLANE + (unsigned)(row * 80 + seg * 2);
        } else {
            int idx = task - 512;
            int plane = idx >> 8; idx &= 255;
            int n = idx >> 2, seg = (idx & 3) << 3;
            int j;
            if (lstm) {
                // gate = 2*bit3(n) + bit0(n); cell = ubj + 4*bits[5:4](n) + bits[2:1](n)
                int gate = (((n >> 3) & 1) << 1) | (n & 1);
                int cell = ubj + ((n >> 4) << 2) + ((n >> 1) & 3);
                j = gate * HH + cell;
            } else {
                j = ubj + n;
            }
            src = (plane ? wl : wh) + (long)j * ldw + k0 + seg;
            dst = dstbase + B_BASE + plane * B_PLANE + (unsigned)(n * 80 + seg * 2);
        }
        asm volatile("cp.async.cg.shared.global [%0],[%1],16;" :: "r"(dst), "l"(src) : "memory");
    }
}

__device__ __forceinline__ void ldm4(unsigned& r0, unsigned& r1, unsigned& r2, unsigned& r3,
                                     unsigned addr) {
    asm volatile("ldmatrix.sync.aligned.m8n8.x4.shared.b16 {%0,%1,%2,%3},[%4];"
                 : "=r"(r0), "=r"(r1), "=r"(r2), "=r"(r3) : "r"(addr));
}

__device__ __forceinline__ void mma16816(float* c, unsigned a0, unsigned a1, unsigned a2,
                                         unsigned a3, unsigned b0, unsigned b1) {
    asm volatile("mma.sync.aligned.m16n8k16.row.col.f32.bf16.bf16.f32 "
                 "{%0,%1,%2,%3},{%4,%5,%6,%7},{%8,%9},{%0,%1,%2,%3};"
                 : "+f"(c[0]), "+f"(c[1]), "+f"(c[2]), "+f"(c[3])
                 : "r"(a0), "r"(a1), "r"(a2), "r"(a3), "r"(b0), "r"(b1));
}

// one 32-k chunk: 3-term bf16x3 (hi*hi + hi*lo + lo*hi)
__device__ __forceinline__ void mma_chunk(unsigned sb, float (&acc)[2][2][4],
                                          int lane, int wm, int wn) {
    const unsigned arow = (unsigned)(wm * 32 + (lane & 15));
    const unsigned acs = (unsigned)((lane >> 4) * 8);
    const unsigned bn = (unsigned)(wn * 16 + (lane & 7) + ((lane >> 4) << 3));
    const unsigned bks = (unsigned)(((lane >> 3) & 1) * 8);
#pragma unroll
    for (int kk = 0; kk < 32; kk += 16) {
        unsigned aoff = sb + arow * 80 + (kk + acs) * 2;
        unsigned ah0[4], ah1[4], al0[4], al1[4], bh[4], bl[4];
        ldm4(ah0[0], ah0[1], ah0[2], ah0[3], aoff);
        ldm4(ah1[0], ah1[1], ah1[2], ah1[3], aoff + 16 * 80);
        ldm4(al0[0], al0[1], al0[2], al0[3], aoff + A_PLANE);
        ldm4(al1[0], al1[1], al1[2], al1[3], aoff + A_PLANE + 16 * 80);
        unsigned boff = sb + B_BASE + bn * 80 + (kk + bks) * 2;
        ldm4(bh[0], bh[1], bh[2], bh[3], boff);
        ldm4(bl[0], bl[1], bl[2], bl[3], boff + B_PLANE);
#pragma unroll
        for (int nt = 0; nt < 2; nt++) {
            const int rr = nt * 2;
            mma16816(acc[0][nt], ah0[0], ah0[1], ah0[2], ah0[3], bh[rr], bh[rr + 1]);
            mma16816(acc[0][nt], ah0[0], ah0[1], ah0[2], ah0[3], bl[rr], bl[rr + 1]);
            mma16816(acc[0][nt], al0[0], al0[1], al0[2], al0[3], bh[rr], bh[rr + 1]);
            mma16816(acc[1][nt], ah1[0], ah1[1], ah1[2], ah1[3], bh[rr], bh[rr + 1]);
            mma16816(acc[1][nt], ah1[0], ah1[1], ah1[2], ah1[3], bl[rr], bl[rr + 1]);
            mma16816(acc[1][nt], al1[0], al1[1], al1[2], al1[3], bh[rr], bh[rr + 1]);
        }
    }
}

__device__ __forceinline__ void load_sel(unsigned buf, int c, int n0,
        const bf16* a0h, const bf16* a0l, int lda0,
        const bf16* w0h, const bf16* w0l, int ldw0,
        const bf16* a1h, const bf16* a1l, int lda1,
        const bf16* w1h, const bf16* w1l, int ldw1,
        int arow0, int ubj, bool lstm, int tid) {
    bool r0 = c < n0;
    const bf16* ah = r0 ? a0h : a1h;
    const bf16* al = r0 ? a0l : a1l;
    const bf16* wh = r0 ? w0h : w1h;
    const bf16* wl = r0 ? w0l : w1l;
    int lda = r0 ? lda0 : lda1;
    int ldw = r0 ? ldw0 : ldw1;
    int k0 = (r0 ? c : c - n0) * 32;
    load_chunk(buf, ah, al, lda, wh, wl, ldw, arow0, k0, ubj, lstm, tid);
}

#define LSEL(buf, c) load_sel(buf, c, n0, a0h, a0l, lda0, w0h, w0l, ldw0, \
                              a1h, a1l, lda1, w1h, w1l, ldw1, arow0, ubj, lstm, tid)

// tile GEMM: 64(b) x 64(cols), up to 2 K-regions, 4-deep cp.async ring
__device__ __forceinline__ void gemm2(float (&acc)[2][2][4],
        const bf16* a0h, const bf16* a0l, int lda0,
        const bf16* w0h, const bf16* w0l, int ldw0, int n0,
        const bf16* a1h, const bf16* a1l, int lda1,
        const bf16* w1h, const bf16* w1l, int ldw1, int n1,
        int arow0, int ubj, bool lstm, unsigned sb,
        int tid, int lane, int wm, int wn) {
    const int total = n0 + n1;
    LSEL(sb, 0);
    asm volatile("cp.async.commit_group;" ::: "memory");
    LSEL(sb + CH_BYTES, 1);
    asm volatile("cp.async.commit_group;" ::: "memory");
    for (int c = 0; c < total; c++) {
        int cn = c + 2;
        if (cn < total) LSEL(sb + (unsigned)(cn & 3) * CH_BYTES, cn);
        asm volatile("cp.async.commit_group;" ::: "memory");
        asm volatile("cp.async.wait_group 2;" ::: "memory");
        __syncthreads();
        mma_chunk(sb + (unsigned)(c & 3) * CH_BYTES, acc, lane, wm, wn);
    }
}

// LSTM epilogue: 4 (b,cell) pairs per thread, all 4 gates in registers
__device__ __forceinline__ void lstm_epi(float (&acc)[2][2][4],
        float* cbuf, bf16* hhi, bf16* hlo,
        const float* bih, const float* bhh, const float* w1, bool dorelu,
        int b_base, int uc_base, int lane, int wm, int wn) {
    const int q = lane & 3, rw = lane >> 2;
    const int uc = uc_base + wn * 4 + q;
    const float b0 = __ldg(bih + 0 * HH + uc) + __ldg(bhh + 0 * HH + uc);
    const float b1 = __ldg(bih + 1 * HH + uc) + __ldg(bhh + 1 * HH + uc);
    const float b2 = __ldg(bih + 2 * HH + uc) + __ldg(bhh + 2 * HH + uc);
    const float b3 = __ldg(bih + 3 * HH + uc) + __ldg(bhh + 3 * HH + uc);
    float w0v = 0.f, w1v = 0.f, w2v = 0.f, w3v = 0.f;
    if (w1) {
        w0v = __ldg(w1 + 0 * HH + uc); w1v = __ldg(w1 + 1 * HH + uc);
        w2v = __ldg(w1 + 2 * HH + uc); w3v = __ldg(w1 + 3 * HH + uc);
    }
#pragma unroll
    for (int mt = 0; mt < 2; mt++) {
#pragma unroll
        for (int hf = 0; hf < 2; hf++) {
            const int b = b_base + wm * 32 + mt * 16 + hf * 8 + rw;
            const int k = hf * 2;
            float iv = acc[mt][0][k]     + b0;
            float fv = acc[mt][0][k + 1] + b1;
            float gv = acc[mt][1][k]     + b2;
            float ov = acc[mt][1][k + 1] + b3;
            if (w1) {
                float xi = __ldcg(&g_x[b]);
                iv += xi * w0v; fv += xi * w1v; gv += xi * w2v; ov += xi * w3v;
            }
            iv = sigm(iv); fv = sigm(fv); gv = tanh_f(gv); ov = sigm(ov);
            const long co = (long)b * HH + uc;
            float cc = __ldcg(cbuf + co);
            float cn = fv * cc + iv * gv;
            __stcg(cbuf + co, cn);
            float h = ov * tanh_f(cn);
            bf16 hh = __float2bfloat16_rn(h);
            st16cg(hhi + co, hh);
            st16cg(hlo + co, __float2bfloat16_rn(h - __bfloat162float(hh)));
            if (dorelu) {
                float r = fmaxf(h, 0.f);
                bf16 rh = __float2bfloat16_rn(r);
                st16cg(g_rhhi + co, rh);
                st16cg(g_rhlo + co, __float2bfloat16_rn(r - __bfloat162float(rh)));
            }
        }
    }
}

// ---------------- prologue kernels ----------------
__global__ void split_kernel(const float* __restrict__ s, long n, int id) {
    bf16 *hi, *lo;
    switch (id) {
        case 0: hi = s_hi;    lo = s_lo;    break;
        case 1: hi = w_e0i_h; lo = w_e0i_l; break;
        case 2: hi = w_e0h_h; lo = w_e0h_l; break;
        case 3: hi = w_e1i_h; lo = w_e1i_l; break;
        case 4: hi = w_e1h_h; lo = w_e1h_l; break;
        case 5: hi = w_d0h_h; lo = w_d0h_l; break;
        case 6: hi = w_d1i_h; lo = w_d1i_l; break;
        case 7: hi = w_d1h_h; lo = w_d1h_l; break;
        default: hi = w_f0_h; lo = w_f0_l;  break;
    }
    long i = (long)blockIdx.x * blockDim.x + threadIdx.x;
    long stride = (long)gridDim.x * blockDim.x;
    for (; i < n; i += stride) {
        float v = s[i];
        bf16 h = __float2bfloat16_rn(v);
        hi[i] = h;
        lo[i] = __float2bfloat16_rn(v - __bfloat162float(h));
    }
}

__global__ void reset_kernel(const float* __restrict__ tgt) {
    long idx = (long)blockIdx.x * blockDim.x + threadIdx.x;
    long stride = (long)gridDim.x * blockDim.x;
    unsigned* hh = (unsigned*)&g_hhi[0][0][0];
    unsigned* hl = (unsigned*)&g_hlo[0][0][0];
    for (long i = idx; i < 2L * 2 * BB * HH / 2; i += stride) { hh[i] = 0u; hl[i] = 0u; }
    float* cp = &g_c2[0][0];
    for (long i = idx; i < 2L * BB * HH; i += stride) cp[i] = 0.f;
    if (idx < BB) g_x[idx] = tgt[idx * TGTT];
    if (idx == 0) { g_count = 0u; g_sense = 0u; }
}

// ---------------- main persistent kernel ----------------
__global__ __launch_bounds__(NTHR, 1) void seq2seq_kernel(
    const float* __restrict__ ebih0, const float* __restrict__ ebhh0,
    const float* __restrict__ ebih1, const float* __restrict__ ebhh1,
    const float* __restrict__ dWih0,
    const float* __restrict__ dbih0, const float* __restrict__ dbhh0,
    const float* __restrict__ dbih1, const float* __restrict__ dbhh1,
    const float* __restrict__ fb0,
    const float* __restrict__ fW1, const float* __restrict__ fb1,
    float* __restrict__ out) {
    extern __shared__ char dsm[];
    unsigned sb;
    asm("{.reg .u64 t; cvta.to.shared.u64 t, %1; cvt.u32.u64 %0,t;}" : "=r"(sb) : "l"(dsm));

    const int tid = threadIdx.x;
    const int lane = tid & 31, wid = tid >> 5;
    const int wm = wid & 1, wn = wid >> 1;      // 2 x 4 warp grid (32b x 16n per warp)

    const int b_base = (blockIdx.x >> 5) * 64;  // 4 batch tiles of 64
    const int uc_base = (blockIdx.x & 31) * 16; // 32 cell tiles of 16

    int par = 0;

    // ---------------- encoder ----------------
    for (int t = 0; t < SRCT; t++) {
        {   // L0: src (K=64) + h0 (K=512)
            float acc[2][2][4] = {};
            gemm2(acc, s_hi + t * INP, s_lo + t * INP, SRCT * INP,
                  w_e0i_h, w_e0i_l, INP, 2,
                  g_hhi[0][par], g_hlo[0][par], HH, w_e0h_h, w_e0h_l, HH, 16,
                  b_base, uc_base, true, sb, tid, lane, wm, wn);
            lstm_epi(acc, g_c2[0], g_hhi[0][par ^ 1], g_hlo[0][par ^ 1],
                     ebih0, ebhh0, nullptr, false, b_base, uc_base, lane, wm, wn);
        }
        gsync();
        {   // L1: h0_new (K=512) + h1 (K=512)
            float acc[2][2][4] = {};
            gemm2(acc, g_hhi[0][par ^ 1], g_hlo[0][par ^ 1], HH,
                  w_e1i_h, w_e1i_l, HH, 16,
                  g_hhi[1][par], g_hlo[1][par], HH, w_e1h_h, w_e1h_l, HH, 16,
                  b_base, uc_base, true, sb, tid, lane, wm, wn);
            lstm_epi(acc, g_c2[1], g_hhi[1][par ^ 1], g_hlo[1][par ^ 1],
                     ebih1, ebhh1, nullptr, false, b_base, uc_base, lane, wm, wn);
        }
        gsync();
        par ^= 1;
    }

    // ---------------- decoder ----------------
    for (int t = 0; t < TGTT; t++) {
        {   // L0: rank-1 scalar input (epilogue) + h0 (K=512)
            float acc[2][2][4] = {};
            gemm2(acc, g_hhi[0][par], g_hlo[0][par], HH,
                  w_d0h_h, w_d0h_l, HH, 16,
                  g_hhi[0][par], g_hlo[0][par], HH, w_d0h_h, w_d0h_l, HH, 0,
                  b_base, uc_base, true, sb, tid, lane, wm, wn);
            lstm_epi(acc, g_c2[0], g_hhi[0][par ^ 1], g_hlo[0][par ^ 1],
                     dbih0, dbhh0, dWih0, false, b_base, uc_base, lane, wm, wn);
        }
        gsync();
        {   // L1: h0_new + h1; also emits relu(h1) split for fc0
            float acc[2][2][4] = {};
            gemm2(acc, g_hhi[0][par ^ 1], g_hlo[0][par ^ 1], HH,
                  w_d1i_h, w_d1i_l, HH, 16,
                  g_hhi[1][par], g_hlo[1][par], HH, w_d1h_h, w_d1h_l, HH, 16,
                  b_base, uc_base, true, sb, tid, lane, wm, wn);
            lstm_epi(acc, g_c2[1], g_hhi[1][par ^ 1], g_hlo[1][par ^ 1],
                     dbih1, dbhh1, nullptr, true, b_base, uc_base, lane, wm, wn);
        }
        gsync();

        // fc0: g_fc = relu(relu(h1) @ fW0^T + b0). blocks 0..31, tile 64x64.
        if (blockIdx.x < 32) {
            const int fb = (blockIdx.x >> 3) * 64;
            const int fcb = (blockIdx.x & 7) * 64;
            float acc[2][2][4] = {};
            gemm2(acc, g_rhhi, g_rhlo, HH, w_f0_h, w_f0_l, HH, 16,
                  g_rhhi, g_rhlo, HH, w_f0_h, w_f0_l, HH, 0,
                  fb, fcb, false, sb, tid, lane, wm, wn);
            const int q = lane & 3, rw = lane >> 2;
#pragma unroll
            for (int mt = 0; mt < 2; mt++) {
#pragma unroll
                for (int hf = 0; hf < 2; hf++) {
                    const int b = fb + wm * 32 + mt * 16 + hf * 8 + rw;
                    const int k = hf * 2;
#pragma unroll
                    for (int nt = 0; nt < 2; nt++) {
#pragma unroll
                        for (int c2 = 0; c2 < 2; c2++) {
                            const int col = fcb + wn * 16 + nt * 8 + q * 2 + c2;
                            float v = fmaxf(acc[mt][nt][k + c2] + __ldg(fb0 + col), 0.f);
                            __stcg(g_fc + (long)b * HH + col, v);
                        }
                    }
                }
            }
        }
        gsync();

        // fc1: out[b] = g_fc[b] . W1 + b1 ; becomes next decoder input
        if (blockIdx.x == 0) {
            const int b = tid;
            const float4* tp = (const float4*)(g_fc + (long)b * HH);
            const float4* wp = (const float4*)fW1;
            float s0 = 0.f, s1 = 0.f, s2 = 0.f, s3 = 0.f;
#pragma unroll 8
            for (int kq = 0; kq < HH / 4; kq++) {
                float4 v = __ldcg(tp + kq);
                float4 w = __ldg(wp + kq);
                s0 += v.x * w.x; s1 += v.y * w.y;
                s2 += v.z * w.z; s3 += v.w * w.w;
            }
            float o = (s0 + s1) + (s2 + s3) + __ldg(fb1);
            out[(long)b * TGTT + t] = o;
            __stcg(&g_x[b], o);
        }
        gsync();
        par ^= 1;
    }
}

// ---------------- launch ----------------
extern "C" void kernel_launch(void* const* d_in, const int* in_sizes, int n_in,
                              void* d_out, int out_size) {
    const float* src   = (const float*)d_in[0];
    const float* tgt   = (const float*)d_in[1];
    const float* eWih0 = (const float*)d_in[2];
    const float* eWhh0 = (const float*)d_in[3];
    const float* ebih0 = (const float*)d_in[4];
    const float* ebhh0 = (const float*)d_in[5];
    const float* dWih0 = (const float*)d_in[6];
    const float* dWhh0 = (const float*)d_in[7];
    const float* dbih0 = (const float*)d_in[8];
    const float* dbhh0 = (const float*)d_in[9];
    const float* eWih1 = (const float*)d_in[10];
    const float* eWhh1 = (const float*)d_in[11];
    const float* ebih1 = (const float*)d_in[12];
    const float* ebhh1 = (const float*)d_in[13];
    const float* dWih1 = (const float*)d_in[14];
    const float* dWhh1 = (const float*)d_in[15];
    const float* dbih1 = (const float*)d_in[16];
    const float* dbhh1 = (const float*)d_in[17];
    const float* fW0   = (const float*)d_in[18];
    const float* fb0   = (const float*)d_in[19];
    const float* fW1   = (const float*)d_in[20];
    const float* fb1   = (const float*)d_in[21];
    float* out = (float*)d_out;

    cudaFuncSetAttribute(seq2seq_kernel, cudaFuncAttributeMaxDynamicSharedMemorySize, SMEM_BYTES);

    split_kernel<<<2048, 256>>>(src,   (long)BB * SRCT * INP, 0);
    split_kernel<<<256,  256>>>(eWih0, (long)G4 * INP, 1);
    split_kernel<<<1024, 256>>>(eWhh0, (long)G4 * HH, 2);
    split_kernel<<<1024, 256>>>(eWih1, (long)G4 * HH, 3);
    split_kernel<<<1024, 256>>>(eWhh1, (long)G4 * HH, 4);
    split_kernel<<<1024, 256>>>(dWhh0, (long)G4 * HH, 5);
    split_kernel<<<1024, 256>>>(dWih1, (long)G4 * HH, 6);
    split_kernel<<<1024, 256>>>(dWhh1, (long)G4 * HH, 7);
    split_kernel<<<512,  256>>>(fW0,   (long)HH * HH, 8);
    reset_kernel<<<256, 256>>>(tgt);
    seq2seq_kernel<<<NBLK, NTHR, SMEM_BYTES>>>(
        ebih0, ebhh0, ebih1, ebhh1, dWih0, dbih0, dbhh0, dbih1, dbhh1,
        fb0, fW1, fb1, out);
}

// round 8
// speedup vs baseline: 3.6576x; 1.4972x over previous
#include <cuda_runtime.h>
#include <cuda_bf16.h>

#define BB    256
#define HH    512
#define G4    2048
#define SRCT  512
#define INP   64
#define TGTT  96
#define NBLK  128
#define NTHR  256

typedef __nv_bfloat16 bf16;

// phase buffer: A_hi[64][72] | A_lo | B_hi[64][72] | B_lo  (bf16, row 144B)
#define ROWB      144u
#define PLANE     9216u        // 64*144
#define BOFF      18432u
#define PH_BYTES  36864u
#define NBUF      4
#define SMEM_BYTES (NBUF * PH_BYTES)   // 147456

// ---------------- device globals ----------------
static __device__ __align__(16) bf16 s_hi[(long)BB*SRCT*INP], s_lo[(long)BB*SRCT*INP];
static __device__ __align__(16) bf16 w_e0i_h[G4*INP], w_e0i_l[G4*INP];
static __device__ __align__(16) bf16 w_e0h_h[G4*HH],  w_e0h_l[G4*HH];
static __device__ __align__(16) bf16 w_e1i_h[G4*HH],  w_e1i_l[G4*HH];
static __device__ __align__(16) bf16 w_e1h_h[G4*HH],  w_e1h_l[G4*HH];
static __device__ __align__(16) bf16 w_d0h_h[G4*HH],  w_d0h_l[G4*HH];
static __device__ __align__(16) bf16 w_d1i_h[G4*HH],  w_d1i_l[G4*HH];
static __device__ __align__(16) bf16 w_d1h_h[G4*HH],  w_d1h_l[G4*HH];
static __device__ __align__(16) bf16 w_f0_h[HH*HH],   w_f0_l[HH*HH];
static __device__ __align__(16) bf16 g_hhi[2][2][BB*HH], g_hlo[2][2][BB*HH];
static __device__ __align__(16) bf16 g_rhhi[BB*HH], g_rhlo[BB*HH];
static __device__ __align__(16) float g_x[BB];
static __device__ __align__(16) float g_fc[BB*HH];
static __device__ unsigned g_count;
static __device__ volatile unsigned g_sense;

// ---------------- helpers ----------------
__device__ __forceinline__ float sigm(float x) { return 1.0f / (1.0f + __expf(-x)); }
__device__ __forceinline__ float tanh_f(float x) { return 2.0f / (1.0f + __expf(-2.0f * x)) - 1.0f; }

__device__ __forceinline__ void gsync() {
    __threadfence();
    __syncthreads();
    if (threadIdx.x == 0) {
        unsigned a = atomicAdd(&g_count, 1u);
        unsigned target = a / NBLK + 1u;
        if ((a % NBLK) == (NBLK - 1)) {
            __threadfence();
            g_sense = target;
        } else {
            while (g_sense < target) { __nanosleep(32); }
        }
        __threadfence();
    }
    __syncthreads();
}

__device__ __forceinline__ void st16cg(bf16* p, bf16 v) {
    unsigned short u = __bfloat16_as_ushort(v);
    asm volatile("st.global.cg.u16 [%0], %1;" :: "l"(p), "h"(u) : "memory");
}

// 2048 cp.async tasks (K=64 phase): A 64r x 8seg x {hi,lo}; B same
__device__ __forceinline__ void load_phase(unsigned dstbase,
        const bf16* ah, const bf16* al, int lda,
        const bf16* wh, const bf16* wl, int ldw,
        int arow0, int k0, int ubj, bool lstm, int tid) {
#pragma unroll
    for (int it = 0; it < 8; it++) {
        int task = tid + it * NTHR;
        const bf16* src;
        unsigned dst;
        if (task < 1024) {
            int plane = task >> 9, idx = task & 511;
            int row = idx >> 3, seg = (idx & 7) << 3;
            src = (plane ? al : ah) + (long)(arow0 + row) * lda + k0 + seg;
            dst = dstbase + plane * PLANE + (unsigned)(row * ROWB + seg * 2);
        } else {
            int idx = task - 1024;
            int plane = idx >> 9; idx &= 511;
            int n = idx >> 3, seg = (idx & 7) << 3;
            int j;
            if (lstm) {
                int gate = (((n >> 3) & 1) << 1) | (n & 1);
                int cell = ubj + ((n >> 4) << 2) + ((n >> 1) & 3);
                j = gate * HH + cell;
            } else {
                j = ubj + n;
            }
            src = (plane ? wl : wh) + (long)j * ldw + k0 + seg;
            dst = dstbase + BOFF + plane * PLANE + (unsigned)(n * ROWB + seg * 2);
        }
        asm volatile("cp.async.cg.shared.global [%0],[%1],16;" :: "r"(dst), "l"(src) : "memory");
    }
}

__device__ __forceinline__ void ldm4(unsigned& r0, unsigned& r1, unsigned& r2, unsigned& r3,
                                     unsigned addr) {
    asm volatile("ldmatrix.sync.aligned.m8n8.x4.shared.b16 {%0,%1,%2,%3},[%4];"
                 : "=r"(r0), "=r"(r1), "=r"(r2), "=r"(r3) : "r"(addr));
}

__device__ __forceinline__ void mma16816(float* c, unsigned a0, unsigned a1, unsigned a2,
                                         unsigned a3, unsigned b0, unsigned b1) {
    asm volatile("mma.sync.aligned.m16n8k16.row.col.f32.bf16.bf16.f32 "
                 "{%0,%1,%2,%3},{%4,%5,%6,%7},{%8,%9},{%0,%1,%2,%3};"
                 : "+f"(c[0]), "+f"(c[1]), "+f"(c[2]), "+f"(c[3])
                 : "r"(a0), "r"(a1), "r"(a2), "r"(a3), "r"(b0), "r"(b1));
}

// one K=64 phase: warp tile 32(m) x 16(n), bf16x3 (hi*hi + hi*lo + lo*hi)
__device__ __forceinline__ void mma_phase(unsigned sb, float (&acc)[2][2][4],
                                          int lane, int wm, int wn) {
    const unsigned arow = (unsigned)(wm * 32 + (lane & 15));
    const unsigned acs = (unsigned)((lane >> 4) * 8);
    const unsigned bn = (unsigned)(wn * 16 + (lane & 7) + ((lane >> 4) << 3));
    const unsigned bks = (unsigned)(((lane >> 3) & 1) * 8);
#pragma unroll
    for (int kk = 0; kk < 64; kk += 16) {
        unsigned ah0[4], ah1[4], al0[4], al1[4], bh[4], bl[4];
        unsigned aoff = sb + arow * ROWB + (kk + acs) * 2;
        ldm4(ah0[0], ah0[1], ah0[2], ah0[3], aoff);
        ldm4(ah1[0], ah1[1], ah1[2], ah1[3], aoff + 16 * ROWB);
        ldm4(al0[0], al0[1], al0[2], al0[3], aoff + PLANE);
        ldm4(al1[0], al1[1], al1[2], al1[3], aoff + PLANE + 16 * ROWB);
        unsigned boff = sb + BOFF + bn * ROWB + (kk + bks) * 2;
        ldm4(bh[0], bh[1], bh[2], bh[3], boff);
        ldm4(bl[0], bl[1], bl[2], bl[3], boff + PLANE);
#pragma unroll
        for (int nt = 0; nt < 2; nt++) {
            const int rr = nt * 2;
            mma16816(acc[0][nt], ah0[0], ah0[1], ah0[2], ah0[3], bh[rr], bh[rr + 1]);
            mma16816(acc[0][nt], ah0[0], ah0[1], ah0[2], ah0[3], bl[rr], bl[rr + 1]);
            mma16816(acc[0][nt], al0[0], al0[1], al0[2], al0[3], bh[rr], bh[rr + 1]);
            mma16816(acc[1][nt], ah1[0], ah1[1], ah1[2], ah1[3], bh[rr], bh[rr + 1]);
            mma16816(acc[1][nt], ah1[0], ah1[1], ah1[2], ah1[3], bl[rr], bl[rr + 1]);
            mma16816(acc[1][nt], al1[0], al1[1], al1[2], al1[3], bh[rr], bh[rr + 1]);
        }
    }
}

__device__ __forceinline__ void load_sel(unsigned buf, int c, int n0,
        const bf16* a0h, const bf16* a0l, int lda0,
        const bf16* w0h, const bf16* w0l, int ldw0,
        const bf16* a1h, const bf16* a1l, int lda1,
        const bf16* w1h, const bf16* w1l, int ldw1,
        int arow0, int ubj, bool lstm, int tid) {
    bool r0 = c < n0;
    const bf16* ah = r0 ? a0h : a1h;
    const bf16* al = r0 ? a0l : a1l;
    const bf16* wh = r0 ? w0h : w1h;
    const bf16* wl = r0 ? w0l : w1l;
    int lda = r0 ? lda0 : lda1;
    int ldw = r0 ? ldw0 : ldw1;
    int k0 = (r0 ? c : c - n0) * 64;
    load_phase(buf, ah, al, lda, wh, wl, ldw, arow0, k0, ubj, lstm, tid);
}

#define LSEL(buf, c) load_sel(buf, c, n0, a0h, a0l, lda0, w0h, w0l, ldw0, \
                              a1h, a1l, lda1, w1h, w1l, ldw1, arow0, ubj, lstm, tid)

// tile GEMM: 64(b) x 64(cols), up to 2 K-regions, 4-deep ring, K=64 phases
__device__ __forceinline__ void gemm2(float (&acc)[2][2][4],
        const bf16* a0h, const bf16* a0l, int lda0,
        const bf16* w0h, const bf16* w0l, int ldw0, int n0,
        const bf16* a1h, const bf16* a1l, int lda1,
        const bf16* w1h, const bf16* w1l, int ldw1, int n1,
        int arow0, int ubj, bool lstm, unsigned sb,
        int tid, int lane, int wm, int wn) {
    const int total = n0 + n1;
    LSEL(sb, 0);
    asm volatile("cp.async.commit_group;" ::: "memory");
    LSEL(sb + PH_BYTES, 1);
    asm volatile("cp.async.commit_group;" ::: "memory");
    for (int c = 0; c < total; c++) {
        int cn = c + 2;
        if (cn < total) LSEL(sb + (unsigned)(cn & 3) * PH_BYTES, cn);
        asm volatile("cp.async.commit_group;" ::: "memory");
        asm volatile("cp.async.wait_group 2;" ::: "memory");
        __syncthreads();
        mma_phase(sb + (unsigned)(c & 3) * PH_BYTES, acc, lane, wm, wn);
    }
}

// LSTM epilogue: 4 (b,cell) pairs per thread; c-state lives in registers
__device__ __forceinline__ void lstm_epi(float (&acc)[2][2][4], float (&creg)[2][2],
        bf16* hhi, bf16* hlo,
        const float* bih, const float* bhh, const float* w1, bool dorelu,
        int b_base, int uc_base, int lane, int wm, int wn) {
    const int q = lane & 3, rw = lane >> 2;
    const int uc = uc_base + wn * 4 + q;
    const float b0 = __ldg(bih + 0 * HH + uc) + __ldg(bhh + 0 * HH + uc);
    const float b1 = __ldg(bih + 1 * HH + uc) + __ldg(bhh + 1 * HH + uc);
    const float b2 = __ldg(bih + 2 * HH + uc) + __ldg(bhh + 2 * HH + uc);
    const float b3 = __ldg(bih + 3 * HH + uc) + __ldg(bhh + 3 * HH + uc);
    float w0v = 0.f, w1v = 0.f, w2v = 0.f, w3v = 0.f;
    if (w1) {
        w0v = __ldg(w1 + 0 * HH + uc); w1v = __ldg(w1 + 1 * HH + uc);
        w2v = __ldg(w1 + 2 * HH + uc); w3v = __ldg(w1 + 3 * HH + uc);
    }
#pragma unroll
    for (int mt = 0; mt < 2; mt++) {
#pragma unroll
        for (int hf = 0; hf < 2; hf++) {
            const int b = b_base + wm * 32 + mt * 16 + hf * 8 + rw;
            const int k = hf * 2;
            float iv = acc[mt][0][k] + b0;
            float fv = acc[mt][0][k + 1] + b1;
            float gv = acc[mt][1][k] + b2;
            float ov = acc[mt][1][k + 1] + b3;
            if (w1) {
                float xi = __ldcg(&g_x[b]);
                iv += xi * w0v; fv += xi * w1v; gv += xi * w2v; ov += xi * w3v;
            }
            iv = sigm(iv); fv = sigm(fv); gv = tanh_f(gv); ov = sigm(ov);
            float cn = fv * creg[mt][hf] + iv * gv;
            creg[mt][hf] = cn;
            float h = ov * tanh_f(cn);
            const long co = (long)b * HH + uc;
            bf16 hh = __float2bfloat16_rn(h);
            st16cg(hhi + co, hh);
            st16cg(hlo + co, __float2bfloat16_rn(h - __bfloat162float(hh)));
            if (dorelu) {
                float r = fmaxf(h, 0.f);
                bf16 rh = __float2bfloat16_rn(r);
                st16cg(g_rhhi + co, rh);
                st16cg(g_rhlo + co, __float2bfloat16_rn(r - __bfloat162float(rh)));
            }
        }
    }
}

// ---------------- prologue kernels ----------------
__global__ void split_kernel(const float* __restrict__ s, long n, int id) {
    bf16 *hi, *lo;
    switch (id) {
        case 0: hi = s_hi;    lo = s_lo;    break;
        case 1: hi = w_e0i_h; lo = w_e0i_l; break;
        case 2: hi = w_e0h_h; lo = w_e0h_l; break;
        case 3: hi = w_e1i_h; lo = w_e1i_l; break;
        case 4: hi = w_e1h_h; lo = w_e1h_l; break;
        case 5: hi = w_d0h_h; lo = w_d0h_l; break;
        case 6: hi = w_d1i_h; lo = w_d1i_l; break;
        case 7: hi = w_d1h_h; lo = w_d1h_l; break;
        default: hi = w_f0_h; lo = w_f0_l;  break;
    }
    long i = (long)blockIdx.x * blockDim.x + threadIdx.x;
    long stride = (long)gridDim.x * blockDim.x;
    for (; i < n; i += stride) {
        float v = s[i];
        bf16 h = __float2bfloat16_rn(v);
        hi[i] = h;
        lo[i] = __float2bfloat16_rn(v - __bfloat162float(h));
    }
}

__global__ void reset_kernel(const float* __restrict__ tgt) {
    long idx = (long)blockIdx.x * blockDim.x + threadIdx.x;
    long stride = (long)gridDim.x * blockDim.x;
    unsigned* hh = (unsigned*)&g_hhi[0][0][0];
    unsigned* hl = (unsigned*)&g_hlo[0][0][0];
    for (long i = idx; i < 2L * 2 * BB * HH / 2; i += stride) { hh[i] = 0u; hl[i] = 0u; }
    if (idx < BB) g_x[idx] = tgt[idx * TGTT];
    if (idx == 0) { g_count = 0u; g_sense = 0u; }
}

// ---------------- main persistent kernel ----------------
__global__ __launch_bounds__(NTHR, 1) void seq2seq_kernel(
    const float* __restrict__ ebih0, const float* __restrict__ ebhh0,
    const float* __restrict__ ebih1, const float* __restrict__ ebhh1,
    const float* __restrict__ dWih0,
    const float* __restrict__ dbih0, const float* __restrict__ dbhh0,
    const float* __restrict__ dbih1, const float* __restrict__ dbhh1,
    const float* __restrict__ fb0,
    const float* __restrict__ fW1, const float* __restrict__ fb1,
    float* __restrict__ out) {
    extern __shared__ char dsm[];
    unsigned sb;
    asm("{.reg .u64 t; cvta.to.shared.u64 t, %1; cvt.u32.u64 %0,t;}" : "=r"(sb) : "l"(dsm));

    const int tid = threadIdx.x;
    const int lane = tid & 31, wid = tid >> 5;
    const int wm = wid & 1, wn = wid >> 1;      // 2 x 4 warp grid, warp tile 32x16

    const int b_base = (blockIdx.x >> 5) * 64;
    const int uc_base = (blockIdx.x & 31) * 16;

    float c_l0[2][2] = {{0.f, 0.f}, {0.f, 0.f}};
    float c_l1[2][2] = {{0.f, 0.f}, {0.f, 0.f}};

    // ---------------- encoder (wavefront: L0(s) and L1(s-1) per step) --------
    for (int s = 0; s <= SRCT; s++) {
        if (s < SRCT) {       // L0 at t=s
            float acc[2][2][4] = {};
            gemm2(acc, s_hi + s * INP, s_lo + s * INP, SRCT * INP,
                  w_e0i_h, w_e0i_l, INP, 1,
                  g_hhi[0][(s + 1) & 1], g_hlo[0][(s + 1) & 1], HH,
                  w_e0h_h, w_e0h_l, HH, 8,
                  b_base, uc_base, true, sb, tid, lane, wm, wn);
            lstm_epi(acc, c_l0, g_hhi[0][s & 1], g_hlo[0][s & 1],
                     ebih0, ebhh0, nullptr, false, b_base, uc_base, lane, wm, wn);
        }
        if (s > 0) {          // L1 at t=s-1
            const int t = s - 1;
            float acc[2][2][4] = {};
            gemm2(acc, g_hhi[0][t & 1], g_hlo[0][t & 1], HH,
                  w_e1i_h, w_e1i_l, HH, 8,
                  g_hhi[1][(t + 1) & 1], g_hlo[1][(t + 1) & 1], HH,
                  w_e1h_h, w_e1h_l, HH, 8,
                  b_base, uc_base, true, sb, tid, lane, wm, wn);
            lstm_epi(acc, c_l1, g_hhi[1][t & 1], g_hlo[1][t & 1],
                     ebih1, ebhh1, nullptr, false, b_base, uc_base, lane, wm, wn);
        }
        gsync();
    }

    // ---------------- decoder (serial chain, 4 barriers/step) ----------------
    for (int t = 0; t < TGTT; t++) {
        const int p = t & 1, pp = (t + 1) & 1;   // SRCT even: parity continues
        {   // L0: recurrent GEMM + rank-1 x in epilogue
            float acc[2][2][4] = {};
            gemm2(acc, g_hhi[0][pp], g_hlo[0][pp], HH,
                  w_d0h_h, w_d0h_l, HH, 8,
                  g_hhi[0][pp], g_hlo[0][pp], HH, w_d0h_h, w_d0h_l, HH, 0,
                  b_base, uc_base, true, sb, tid, lane, wm, wn);
            lstm_epi(acc, c_l0, g_hhi[0][p], g_hlo[0][p],
                     dbih0, dbhh0, dWih0, false, b_base, uc_base, lane, wm, wn);
        }
        gsync();
        {   // L1: input h0(t) + recurrent h1(t-1); emit relu(h1) too
            float acc[2][2][4] = {};
            gemm2(acc, g_hhi[0][p], g_hlo[0][p], HH,
                  w_d1i_h, w_d1i_l, HH, 8,
                  g_hhi[1][pp], g_hlo[1][pp], HH, w_d1h_h, w_d1h_l, HH, 8,
                  b_base, uc_base, true, sb, tid, lane, wm, wn);
            lstm_epi(acc, c_l1, g_hhi[1][p], g_hlo[1][p],
                     dbih1, dbhh1, nullptr, true, b_base, uc_base, lane, wm, wn);
        }
        gsync();

        // fc0 on blocks 0..31 (tile 64x64)
        if (blockIdx.x < 32) {
            const int fb = (blockIdx.x >> 3) * 64;
            const int fcb = (blockIdx.x & 7) * 64;
            float acc[2][2][4] = {};
            gemm2(acc, g_rhhi, g_rhlo, HH, w_f0_h, w_f0_l, HH, 8,
                  g_rhhi, g_rhlo, HH, w_f0_h, w_f0_l, HH, 0,
                  fb, fcb, false, sb, tid, lane, wm, wn);
            const int q = lane & 3, rw = lane >> 2;
#pragma unroll
            for (int mt = 0; mt < 2; mt++) {
#pragma unroll
                for (int hf = 0; hf < 2; hf++) {
                    const int b = fb + wm * 32 + mt * 16 + hf * 8 + rw;
                    const int k = hf * 2;
#pragma unroll
                    for (int nt = 0; nt < 2; nt++) {
#pragma unroll
                        for (int c2 = 0; c2 < 2; c2++) {
                            const int col = fcb + wn * 16 + nt * 8 + q * 2 + c2;
                            float v = fmaxf(acc[mt][nt][k + c2] + __ldg(fb0 + col), 0.f);
                            __stcg(g_fc + (long)b * HH + col, v);
                        }
                    }
                }
            }
        }
        gsync();

        // fc1 on blocks 0..31: one warp per batch row (32 blk x 8 warps = 256)
        if (blockIdx.x < 32) {
            const int row = blockIdx.x * 8 + wid;
            const float4* tp = (const float4*)(g_fc + (long)row * HH);
            const float4* wp = (const float4*)fW1;
            float s0 = 0.f;
#pragma unroll
            for (int i = 0; i < 4; i++) {
                float4 v = __ldcg(tp + lane + i * 32);
                float4 w = __ldg(wp + lane + i * 32);
                s0 += v.x * w.x + v.y * w.y + v.z * w.z + v.w * w.w;
            }
#pragma unroll
            for (int o = 16; o > 0; o >>= 1) s0 += __shfl_xor_sync(0xffffffffu, s0, o);
            if (lane == 0) {
                float o = s0 + __ldg(fb1);
                out[(long)row * TGTT + t] = o;
                __stcg(&g_x[row], o);
            }
        }
        gsync();
    }
}

// ---------------- launch ----------------
extern "C" void kernel_launch(void* const* d_in, const int* in_sizes, int n_in,
                              void* d_out, int out_size) {
    const float* src   = (const float*)d_in[0];
    const float* tgt   = (const float*)d_in[1];
    const float* eWih0 = (const float*)d_in[2];
    const float* eWhh0 = (const float*)d_in[3];
    const float* ebih0 = (const float*)d_in[4];
    const float* ebhh0 = (const float*)d_in[5];
    const float* dWih0 = (const float*)d_in[6];
    const float* dWhh0 = (const float*)d_in[7];
    const float* dbih0 = (const float*)d_in[8];
    const float* dbhh0 = (const float*)d_in[9];
    const float* eWih1 = (const float*)d_in[10];
    const float* eWhh1 = (const float*)d_in[11];
    const float* ebih1 = (const float*)d_in[12];
    const float* ebhh1 = (const float*)d_in[13];
    const float* dWih1 = (const float*)d_in[14];
    const float* dWhh1 = (const float*)d_in[15];
    const float* dbih1 = (const float*)d_in[16];
    const float* dbhh1 = (const float*)d_in[17];
    const float* fW0   = (const float*)d_in[18];
    const float* fb0   = (const float*)d_in[19];
    const float* fW1   = (const float*)d_in[20];
    const float* fb1   = (const float*)d_in[21];
    float* out = (float*)d_out;

    cudaFuncSetAttribute(seq2seq_kernel, cudaFuncAttributeMaxDynamicSharedMemorySize, SMEM_BYTES);

    split_kernel<<<2048, 256>>>(src,   (long)BB * SRCT * INP, 0);
    split_kernel<<<256,  256>>>(eWih0, (long)G4 * INP, 1);
    split_kernel<<<1024, 256>>>(eWhh0, (long)G4 * HH, 2);
    split_kernel<<<1024, 256>>>(eWih1, (long)G4 * HH, 3);
    split_kernel<<<1024, 256>>>(eWhh1, (long)G4 * HH, 4);
    split_kernel<<<1024, 256>>>(dWhh0, (long)G4 * HH, 5);
    split_kernel<<<1024, 256>>>(dWih1, (long)G4 * HH, 6);
    split_kernel<<<1024, 256>>>(dWhh1, (long)G4 * HH, 7);
    split_kernel<<<512,  256>>>(fW0,   (long)HH * HH, 8);
    reset_kernel<<<256, 256>>>(tgt);
    seq2seq_kernel<<<NBLK, NTHR, SMEM_BYTES>>>(
        ebih0, ebhh0, ebih1, ebhh1, dWih0, dbih0, dbhh0, dbih1, dbhh1,
        fb0, fW1, fb1, out);
}